// round 13
// baseline (speedup 1.0000x reference)
#include <cuda_runtime.h>
#include <stdint.h>

#define QN     256
#define DIM    128
#define NLIST  1024
#define MSUB   8
#define KCODE  256
#define DSUB   16
#define NPROBE 32
#define TOPK   100
#define MAXN   250000
#define CAP    12288
#define DYN_SMEM (CAP * 8)

typedef unsigned long long u64;
typedef unsigned int       u32;

// ---------------- device scratch (static: allocation-free) ------------------
__device__ float g_cnf[NLIST];          // centroid norms (XLA-reduce order)
__device__ int   g_counts[NLIST];
__device__ int   g_starts[NLIST];
__device__ int   g_cursor[NLIST];
__device__ int   g_inv[MAXN];           // point id per inverted slot

// monotonic float->uint transform (total order preserving)
__device__ __forceinline__ u32 f2s(float f) {
    u32 u = __float_as_uint(f);
    return u ^ ((u >> 31) ? 0xFFFFFFFFu : 0x80000000u);
}

// XLA-GPU style row-norm: lane sums 4 CONTIGUOUS rounded products
// sequentially, then shfl-down butterfly (16,8,4,2,1). Valid in lane 0.
__device__ __forceinline__ float warp_norm128(const float* __restrict__ row, int lane)
{
    float p0 = __fmul_rn(row[4 * lane + 0], row[4 * lane + 0]);
    float p1 = __fmul_rn(row[4 * lane + 1], row[4 * lane + 1]);
    float p2 = __fmul_rn(row[4 * lane + 2], row[4 * lane + 2]);
    float p3 = __fmul_rn(row[4 * lane + 3], row[4 * lane + 3]);
    float s  = __fadd_rn(__fadd_rn(__fadd_rn(p0, p1), p2), p3);
    #pragma unroll
    for (int off = 16; off > 0; off >>= 1)
        s = __fadd_rn(s, __shfl_down_sync(0xFFFFFFFFu, s, off));
    return s;
}

// ---------------- index build ------------------------------------------------
__global__ void __launch_bounds__(256) k_cnorm(const float* __restrict__ centroids)
{
    int wid  = blockIdx.x * 8 + (threadIdx.x >> 5);
    int lane = threadIdx.x & 31;
    if (wid < NLIST) {
        float s = warp_norm128(centroids + (size_t)wid * DIM, lane);
        if (lane == 0) g_cnf[wid] = s;
    }
    int gtid = blockIdx.x * 256 + threadIdx.x;
    if (gtid < NLIST) g_counts[gtid] = 0;
}

__global__ void __launch_bounds__(256) k_hist(const int* __restrict__ db_list, int N)
{
    __shared__ int sh[NLIST];
    int t = threadIdx.x;
    for (int i = t; i < NLIST; i += 256) sh[i] = 0;
    __syncthreads();
    for (int n = blockIdx.x * 256 + t; n < N; n += gridDim.x * 256)
        atomicAdd(&sh[db_list[n] & (NLIST - 1)], 1);
    __syncthreads();
    for (int i = t; i < NLIST; i += 256)
        if (sh[i]) atomicAdd(&g_counts[i], sh[i]);
}

__global__ void __launch_bounds__(1024) k_scan()
{
    __shared__ int s[NLIST];
    int t = threadIdx.x;
    int c = g_counts[t];
    s[t] = c;
    __syncthreads();
    for (int off = 1; off < NLIST; off <<= 1) {
        int v = (t >= off) ? s[t - off] : 0;
        __syncthreads();
        s[t] += v;
        __syncthreads();
    }
    g_starts[t] = s[t] - c;
    g_cursor[t] = s[t] - c;
}

__global__ void __launch_bounds__(256) k_scatter(const int* __restrict__ db_list, int N)
{
    for (int n = blockIdx.x * 256 + threadIdx.x; n < N; n += gridDim.x * 256) {
        int l   = db_list[n] & (NLIST - 1);
        int pos = atomicAdd(&g_cursor[l], 1);
        g_inv[pos] = n;
    }
}

// =============================================================================
// k_search: one CTA per query. Dynamic smem: CAP u64 candidate keys (96 KB).
//   phase 1: coarse dists (round-11 numerics) -> register top-32 argmin
//   phase 2: ADC LUT (round-11 numerics)
//   phase 3: SINGLE walk of the 32 inverted lists -> keys at deterministic slots
//   phase 4: exact radix select + compact + bitonic 128 -> top-100 (as float)
// =============================================================================
__global__ void __launch_bounds__(256) k_search(const float* __restrict__ queries,
                                                const float* __restrict__ codebooks,
                                                const float* __restrict__ centroids,
                                                const int*   __restrict__ db_codes,
                                                float* __restrict__ out)
{
    extern __shared__ u64 cand[];            // CAP keys

    __shared__ float lut[MSUB * KCODE];
    __shared__ float qsm[DIM];
    __shared__ u32   hist256[256];
    __shared__ u64   sel[128];
    __shared__ u64   wmin[8];
    __shared__ float s_qnf;
    __shared__ int   s_list[NPROBE], s_start[NPROBE], s_cn[NPROBE], s_pcum[NPROBE + 1];
    __shared__ int   s_cnt, s_k;
    __shared__ u32   s_pfx;

    int t = threadIdx.x;
    int q = blockIdx.x;

    if (t < DIM) qsm[t] = queries[q * DIM + t];
    __syncthreads();

    // ---------- phase 1: coarse distances (reference-order f32) --------------
    if (t < 32) {
        float s = warp_norm128(qsm, t);
        if (t == 0) s_qnf = s;
    }
    __syncthreads();
    float qnf = s_qnf;

    u64 key[4];                               // keys stay in registers
    #pragma unroll
    for (int s = 0; s < 4; ++s) {
        int l = t + s * 256;
        const float* cr = centroids + (size_t)l * DIM;
        float dq = 0.f;                       // sequential FMA, k ascending
        #pragma unroll 8
        for (int d = 0; d < DIM; ++d)
            dq = __fmaf_rn(qsm[d], __ldg(cr + d), dq);
        float dist = __fsub_rn(__fadd_rn(qnf, g_cnf[l]), __fmul_rn(2.f, dq));
        key[s] = (((u64)f2s(dist)) << 32) | (u32)l;
    }

    // exact top-32: 32 rounds of register argmin (2 syncs/round, keys unique)
    for (int r = 0; r < NPROBE; ++r) {
        u64 lm = key[0];
        #pragma unroll
        for (int s = 1; s < 4; ++s) if (key[s] < lm) lm = key[s];
        #pragma unroll
        for (int off = 16; off > 0; off >>= 1) {
            u64 o = __shfl_down_sync(0xFFFFFFFFu, lm, off);
            if (o < lm) lm = o;
        }
        if ((t & 31) == 0) wmin[t >> 5] = lm;
        __syncthreads();
        u64 g = wmin[0];
        #pragma unroll
        for (int w = 1; w < 8; ++w) if (wmin[w] < g) g = wmin[w];
        #pragma unroll
        for (int s = 0; s < 4; ++s)
            if (key[s] == g) key[s] = ~0ULL;
        if (t == 0) s_list[r] = (int)(g & (NLIST - 1));
        __syncthreads();                      // wmin reuse barrier
    }

    if (t < NPROBE) {
        int l = s_list[t];
        s_start[t] = g_starts[l];
        s_cn[t]    = g_counts[l];
    }
    __syncthreads();
    if (t == 0) {
        int acc = 0;
        for (int i = 0; i < NPROBE; ++i) { s_pcum[i] = acc; acc += s_cn[i]; }
        s_pcum[NPROBE] = acc;
    }

    // ---------- phase 2: ADC LUT (reference-order f32) -----------------------
    #pragma unroll
    for (int m = 0; m < MSUB; ++m) {
        const float* cb = codebooks + ((size_t)(m * KCODE + t)) * DSUB;
        const float* qm = qsm + m * DSUB;
        float cn = 0.f, qns = 0.f, dq = 0.f;
        #pragma unroll
        for (int d = 0; d < DSUB; ++d) {
            float c = __ldg(cb + d);
            cn  = __fadd_rn(cn,  __fmul_rn(c, c));
            qns = __fadd_rn(qns, __fmul_rn(qm[d], qm[d]));
            dq  = __fmaf_rn(qm[d], c, dq);
        }
        lut[m * KCODE + t] = __fsub_rn(__fadd_rn(qns, cn), __fmul_rn(2.f, dq));
    }
    __syncthreads();

    // ---------- phase 3: single walk, keys at deterministic slots ------------
    int total = s_pcum[NPROBE];
    int C = (total < CAP) ? total : CAP;
    #pragma unroll 1
    for (int i = 0; i < NPROBE; ++i) {
        int base = s_start[i], cnt = s_cn[i], slot0 = s_pcum[i];
        for (int j = t; j < cnt; j += 256) {
            int slot = slot0 + j;
            if (slot >= CAP) break;
            int n = g_inv[base + j];
            const int4* cp = (const int4*)(db_codes + (size_t)n * MSUB);
            int4 c0 = __ldg(cp);
            int4 c1 = __ldg(cp + 1);
            float dsum = lut[c0.x & 255];          // sequential f32, m = 0..7
            dsum = __fadd_rn(dsum, lut[KCODE     + (c0.y & 255)]);
            dsum = __fadd_rn(dsum, lut[2 * KCODE + (c0.z & 255)]);
            dsum = __fadd_rn(dsum, lut[3 * KCODE + (c0.w & 255)]);
            dsum = __fadd_rn(dsum, lut[4 * KCODE + (c1.x & 255)]);
            dsum = __fadd_rn(dsum, lut[5 * KCODE + (c1.y & 255)]);
            dsum = __fadd_rn(dsum, lut[6 * KCODE + (c1.z & 255)]);
            dsum = __fadd_rn(dsum, lut[7 * KCODE + (c1.w & 255)]);
            cand[slot] = (((u64)f2s(dsum)) << 32) | (u32)n;
        }
    }
    __syncthreads();

    int ksel = (C < TOPK) ? C : TOPK;
    if (C == 0) {
        if (t < TOPK) out[q * TOPK + t] = 0.f;   // unreachable for this data
        return;
    }

    // ---------- phase 4a: exact radix select of ksel-th smallest dist key ----
    if (t == 0) { s_pfx = 0u; s_k = ksel; }
    int iters = (C + 255) >> 8;
    for (int pass = 3; pass >= 0; --pass) {
        __syncthreads();
        u32 prefix = s_pfx;
        int kk     = s_k;
        int shift  = pass * 8;
        u32 pmask  = (pass == 3) ? 0u : (0xFFFFFFFFu << (shift + 8));
        hist256[t] = 0;
        __syncthreads();
        for (int it = 0; it < iters; ++it) {
            int j = (it << 8) + t;
            u32 b = 0xFFFFFFFFu;
            if (j < C) {
                u32 dk = (u32)(cand[j] >> 32);
                if ((dk & pmask) == prefix)
                    b = (dk >> shift) & 0xFF;
            }
            unsigned am = __activemask();
            u32 mm = __match_any_sync(am, b);
            if (b != 0xFFFFFFFFu) {
                int leader = __ffs(mm) - 1;
                if ((t & 31) == leader) atomicAdd(&hist256[b], (u32)__popc(mm));
            }
        }
        __syncthreads();
        for (int off = 1; off < 256; off <<= 1) {
            u32 v = (t >= off) ? hist256[t - off] : 0u;
            __syncthreads();
            hist256[t] += v;
            __syncthreads();
        }
        u32 cum  = hist256[t];
        u32 prev = (t == 0) ? 0u : hist256[t - 1];
        if ((int)cum >= kk && (int)prev < kk) {
            s_pfx = prefix | ((u32)t << shift);
            s_k   = kk - (int)prev;
        }
    }
    __syncthreads();
    u32 kth = s_pfx;

    // ---------- phase 4b: compact (<= kth), bitonic sort 128, emit -----------
    if (t == 0) s_cnt = 0;
    if (t < 128) sel[t] = ~0ULL;
    __syncthreads();
    for (int j = t; j < C; j += 256) {
        u64 k = cand[j];
        if ((u32)(k >> 32) <= kth) {
            int pos = atomicAdd(&s_cnt, 1);
            if (pos < 128) sel[pos] = k;
        }
    }
    __syncthreads();

    for (int kk2 = 2; kk2 <= 128; kk2 <<= 1) {
        for (int jj = kk2 >> 1; jj > 0; jj >>= 1) {
            if (t < 128) {
                int ixj = t ^ jj;
                if (ixj > t) {
                    u64 a = sel[t], b = sel[ixj];
                    bool up = ((t & kk2) == 0);
                    if (up ? (a > b) : (a < b)) { sel[t] = b; sel[ixj] = a; }
                }
            }
            __syncthreads();
        }
    }

    // output buffer is float32 (indices exact below 2^24)
    if (t < TOPK) out[q * TOPK + t] = (float)(u32)(sel[t] & 0xFFFFFFFFu);
}

// =============================================================================
// launch — input mapping verified by round-7 diagnostics (dict order)
// =============================================================================
extern "C" void kernel_launch(void* const* d_in, const int* in_sizes, int n_in,
                              void* d_out, int out_size)
{
    const float* queries   = (const float*)d_in[0];
    const float* centroids = (const float*)d_in[1];
    const float* codebooks = (const float*)d_in[2];
    const int*   db_codes  = (const int*)d_in[3];
    const int*   db_list   = (const int*)d_in[4];
    int N = in_sizes[4];
    if (N <= 0 || N > MAXN) N = MAXN;
    float* out = (float*)d_out;

    cudaFuncSetAttribute(k_search, cudaFuncAttributeMaxDynamicSharedMemorySize,
                         DYN_SMEM);

    k_cnorm<<<128, 256>>>(centroids);
    k_hist<<<128, 256>>>(db_list, N);
    k_scan<<<1, 1024>>>();
    k_scatter<<<128, 256>>>(db_list, N);
    k_search<<<QN, 256, DYN_SMEM>>>(queries, codebooks, centroids, db_codes, out);
}

// round 14
// speedup vs baseline: 1.9995x; 1.9995x over previous
#include <cuda_runtime.h>
#include <stdint.h>

#define QN     256
#define DIM    128
#define NLIST  1024
#define MSUB   8
#define KCODE  256
#define DSUB   16
#define NPROBE 32
#define TOPK   100
#define MAXN   250000
#define CAP    12288
#define DYN_SMEM (CAP * 8)

typedef unsigned long long u64;
typedef unsigned int       u32;

// ---------------- device scratch (static: allocation-free) ------------------
__device__ float g_cnf[NLIST];          // centroid norms (XLA-reduce order)
__device__ float g_ct[DIM * NLIST];     // centroids transposed [d][l]
__device__ int   g_counts[NLIST];
__device__ int   g_starts[NLIST];
__device__ int   g_cursor[NLIST];
__device__ int   g_inv[MAXN];           // point id per inverted slot
__device__ int4  g_codes[2 * MAXN];     // codes gathered into inverted order

// monotonic float->uint transform (total order preserving)
__device__ __forceinline__ u32 f2s(float f) {
    u32 u = __float_as_uint(f);
    return u ^ ((u >> 31) ? 0xFFFFFFFFu : 0x80000000u);
}

// XLA-GPU style row-norm: lane sums 4 CONTIGUOUS rounded products
// sequentially, then shfl-down butterfly (16,8,4,2,1). Valid in lane 0.
__device__ __forceinline__ float warp_norm128(const float* __restrict__ row, int lane)
{
    float p0 = __fmul_rn(row[4 * lane + 0], row[4 * lane + 0]);
    float p1 = __fmul_rn(row[4 * lane + 1], row[4 * lane + 1]);
    float p2 = __fmul_rn(row[4 * lane + 2], row[4 * lane + 2]);
    float p3 = __fmul_rn(row[4 * lane + 3], row[4 * lane + 3]);
    float s  = __fadd_rn(__fadd_rn(__fadd_rn(p0, p1), p2), p3);
    #pragma unroll
    for (int off = 16; off > 0; off >>= 1)
        s = __fadd_rn(s, __shfl_down_sync(0xFFFFFFFFu, s, off));
    return s;
}

// ---------------- build: norms + transpose + zero counts ---------------------
__global__ void __launch_bounds__(256) k_prep(const float* __restrict__ centroids)
{
    int gw   = blockIdx.x * 8 + (threadIdx.x >> 5);   // global warp id
    int lane = threadIdx.x & 31;
    if (gw < NLIST) {
        float s = warp_norm128(centroids + (size_t)gw * DIM, lane);
        if (lane == 0) g_cnf[gw] = s;
    }
    int gtid = blockIdx.x * 256 + threadIdx.x;
    // transpose: out[d*1024 + l] = in[l*128 + d] (writes coalesced)
    for (int i = gtid; i < DIM * NLIST; i += gridDim.x * 256) {
        int d = i >> 10, l = i & (NLIST - 1);
        g_ct[i] = __ldg(centroids + (size_t)l * DIM + d);
    }
    if (gtid < NLIST) g_counts[gtid] = 0;
}

__global__ void __launch_bounds__(256) k_hist(const int* __restrict__ db_list, int N)
{
    __shared__ int sh[NLIST];
    int t = threadIdx.x;
    for (int i = t; i < NLIST; i += 256) sh[i] = 0;
    __syncthreads();
    for (int n = blockIdx.x * 256 + t; n < N; n += gridDim.x * 256)
        atomicAdd(&sh[db_list[n] & (NLIST - 1)], 1);
    __syncthreads();
    for (int i = t; i < NLIST; i += 256)
        if (sh[i]) atomicAdd(&g_counts[i], sh[i]);
}

__global__ void __launch_bounds__(1024) k_scan()
{
    __shared__ int s[NLIST];
    int t = threadIdx.x;
    int c = g_counts[t];
    s[t] = c;
    __syncthreads();
    for (int off = 1; off < NLIST; off <<= 1) {
        int v = (t >= off) ? s[t - off] : 0;
        __syncthreads();
        s[t] += v;
        __syncthreads();
    }
    g_starts[t] = s[t] - c;
    g_cursor[t] = s[t] - c;
}

// one point per thread: short latency chains, full occupancy
__global__ void __launch_bounds__(256) k_scatter(const int* __restrict__ db_list,
                                                 const int* __restrict__ db_codes,
                                                 int N)
{
    int n = blockIdx.x * 256 + threadIdx.x;
    if (n < N) {
        int l   = db_list[n] & (NLIST - 1);
        int pos = atomicAdd(&g_cursor[l], 1);
        const int4* cp = (const int4*)(db_codes + (size_t)n * MSUB);
        g_inv[pos] = n;
        g_codes[2 * pos]     = __ldg(cp);
        g_codes[2 * pos + 1] = __ldg(cp + 1);
    }
}

// =============================================================================
// k_search: one CTA per query. Dynamic smem: CAP u64 candidate keys (96 KB).
//   phase 1: coarse dists from TRANSPOSED centroids (coalesced), seq-FMA order
//   phase 2: ADC LUT (round-11 numerics)
//   phase 3: single walk of 32 inverted lists, coalesced g_codes reads
//   phase 4: exact radix select + compact + bitonic 128 -> top-100 (as float)
// =============================================================================
__global__ void __launch_bounds__(256) k_search(const float* __restrict__ queries,
                                                const float* __restrict__ codebooks,
                                                float* __restrict__ out)
{
    extern __shared__ u64 cand[];            // CAP keys

    __shared__ float lut[MSUB * KCODE];
    __shared__ float qsm[DIM];
    __shared__ u32   hist256[256];
    __shared__ u64   sel[128];
    __shared__ u64   wmin[8];
    __shared__ float s_qnf;
    __shared__ int   s_list[NPROBE], s_start[NPROBE], s_cn[NPROBE], s_pcum[NPROBE + 1];
    __shared__ int   s_cnt, s_k;
    __shared__ u32   s_pfx;

    int t = threadIdx.x;
    int q = blockIdx.x;

    if (t < DIM) qsm[t] = queries[q * DIM + t];
    __syncthreads();

    // ---------- phase 1: coarse distances, coalesced transposed reads --------
    if (t < 32) {
        float s = warp_norm128(qsm, t);
        if (t == 0) s_qnf = s;
    }
    __syncthreads();
    float qnf = s_qnf;

    float dq0 = 0.f, dq1 = 0.f, dq2 = 0.f, dq3 = 0.f;
    #pragma unroll 4
    for (int d = 0; d < DIM; ++d) {          // sequential FMA, d ascending
        float qd = qsm[d];
        const float* row = g_ct + d * NLIST;
        dq0 = __fmaf_rn(qd, __ldg(row + t),       dq0);
        dq1 = __fmaf_rn(qd, __ldg(row + t + 256), dq1);
        dq2 = __fmaf_rn(qd, __ldg(row + t + 512), dq2);
        dq3 = __fmaf_rn(qd, __ldg(row + t + 768), dq3);
    }
    u64 key[4];
    key[0] = (((u64)f2s(__fsub_rn(__fadd_rn(qnf, g_cnf[t      ]), __fmul_rn(2.f, dq0)))) << 32) | (u32)(t);
    key[1] = (((u64)f2s(__fsub_rn(__fadd_rn(qnf, g_cnf[t + 256]), __fmul_rn(2.f, dq1)))) << 32) | (u32)(t + 256);
    key[2] = (((u64)f2s(__fsub_rn(__fadd_rn(qnf, g_cnf[t + 512]), __fmul_rn(2.f, dq2)))) << 32) | (u32)(t + 512);
    key[3] = (((u64)f2s(__fsub_rn(__fadd_rn(qnf, g_cnf[t + 768]), __fmul_rn(2.f, dq3)))) << 32) | (u32)(t + 768);

    // exact top-32: 32 rounds of register argmin (keys unique)
    for (int r = 0; r < NPROBE; ++r) {
        u64 lm = key[0];
        #pragma unroll
        for (int s = 1; s < 4; ++s) if (key[s] < lm) lm = key[s];
        #pragma unroll
        for (int off = 16; off > 0; off >>= 1) {
            u64 o = __shfl_down_sync(0xFFFFFFFFu, lm, off);
            if (o < lm) lm = o;
        }
        if ((t & 31) == 0) wmin[t >> 5] = lm;
        __syncthreads();
        u64 g = wmin[0];
        #pragma unroll
        for (int w = 1; w < 8; ++w) if (wmin[w] < g) g = wmin[w];
        #pragma unroll
        for (int s = 0; s < 4; ++s)
            if (key[s] == g) key[s] = ~0ULL;
        if (t == 0) s_list[r] = (int)(g & (NLIST - 1));
        __syncthreads();                      // wmin reuse barrier
    }

    if (t < NPROBE) {
        int l = s_list[t];
        s_start[t] = g_starts[l];
        s_cn[t]    = g_counts[l];
    }
    __syncthreads();
    if (t == 0) {
        int acc = 0;
        for (int i = 0; i < NPROBE; ++i) { s_pcum[i] = acc; acc += s_cn[i]; }
        s_pcum[NPROBE] = acc;
    }

    // ---------- phase 2: ADC LUT (reference-order f32) -----------------------
    #pragma unroll
    for (int m = 0; m < MSUB; ++m) {
        const float* cb = codebooks + ((size_t)(m * KCODE + t)) * DSUB;
        const float* qm = qsm + m * DSUB;
        float cn = 0.f, qns = 0.f, dq = 0.f;
        #pragma unroll
        for (int d = 0; d < DSUB; ++d) {
            float c = __ldg(cb + d);
            cn  = __fadd_rn(cn,  __fmul_rn(c, c));
            qns = __fadd_rn(qns, __fmul_rn(qm[d], qm[d]));
            dq  = __fmaf_rn(qm[d], c, dq);
        }
        lut[m * KCODE + t] = __fsub_rn(__fadd_rn(qns, cn), __fmul_rn(2.f, dq));
    }
    __syncthreads();

    // ---------- phase 3: single walk, keys at deterministic slots ------------
    int total = s_pcum[NPROBE];
    int C = (total < CAP) ? total : CAP;
    #pragma unroll 1
    for (int i = 0; i < NPROBE; ++i) {
        int base = s_start[i], cnt = s_cn[i], slot0 = s_pcum[i];
        for (int j = t; j < cnt; j += 256) {
            int slot = slot0 + j;
            if (slot >= CAP) break;
            int4 c0 = g_codes[2 * (base + j)];       // coalesced
            int4 c1 = g_codes[2 * (base + j) + 1];
            float dsum = lut[c0.x & 255];            // sequential f32, m = 0..7
            dsum = __fadd_rn(dsum, lut[KCODE     + (c0.y & 255)]);
            dsum = __fadd_rn(dsum, lut[2 * KCODE + (c0.z & 255)]);
            dsum = __fadd_rn(dsum, lut[3 * KCODE + (c0.w & 255)]);
            dsum = __fadd_rn(dsum, lut[4 * KCODE + (c1.x & 255)]);
            dsum = __fadd_rn(dsum, lut[5 * KCODE + (c1.y & 255)]);
            dsum = __fadd_rn(dsum, lut[6 * KCODE + (c1.z & 255)]);
            dsum = __fadd_rn(dsum, lut[7 * KCODE + (c1.w & 255)]);
            cand[slot] = (((u64)f2s(dsum)) << 32) | (u32)g_inv[base + j];
        }
    }
    __syncthreads();

    int ksel = (C < TOPK) ? C : TOPK;
    if (C == 0) {
        if (t < TOPK) out[q * TOPK + t] = 0.f;   // unreachable for this data
        return;
    }

    // ---------- phase 4a: exact radix select of ksel-th smallest dist key ----
    if (t == 0) { s_pfx = 0u; s_k = ksel; }
    int iters = (C + 255) >> 8;
    for (int pass = 3; pass >= 0; --pass) {
        __syncthreads();
        u32 prefix = s_pfx;
        int kk     = s_k;
        int shift  = pass * 8;
        u32 pmask  = (pass == 3) ? 0u : (0xFFFFFFFFu << (shift + 8));
        hist256[t] = 0;
        __syncthreads();
        for (int it = 0; it < iters; ++it) {
            int j = (it << 8) + t;
            u32 b = 0xFFFFFFFFu;
            if (j < C) {
                u32 dk = (u32)(cand[j] >> 32);
                if ((dk & pmask) == prefix)
                    b = (dk >> shift) & 0xFF;
            }
            unsigned am = __activemask();
            u32 mm = __match_any_sync(am, b);
            if (b != 0xFFFFFFFFu) {
                int leader = __ffs(mm) - 1;
                if ((t & 31) == leader) atomicAdd(&hist256[b], (u32)__popc(mm));
            }
        }
        __syncthreads();
        for (int off = 1; off < 256; off <<= 1) {
            u32 v = (t >= off) ? hist256[t - off] : 0u;
            __syncthreads();
            hist256[t] += v;
            __syncthreads();
        }
        u32 cum  = hist256[t];
        u32 prev = (t == 0) ? 0u : hist256[t - 1];
        if ((int)cum >= kk && (int)prev < kk) {
            s_pfx = prefix | ((u32)t << shift);
            s_k   = kk - (int)prev;
        }
    }
    __syncthreads();
    u32 kth = s_pfx;

    // ---------- phase 4b: compact (<= kth), bitonic sort 128, emit -----------
    if (t == 0) s_cnt = 0;
    if (t < 128) sel[t] = ~0ULL;
    __syncthreads();
    for (int j = t; j < C; j += 256) {
        u64 k = cand[j];
        if ((u32)(k >> 32) <= kth) {
            int pos = atomicAdd(&s_cnt, 1);
            if (pos < 128) sel[pos] = k;
        }
    }
    __syncthreads();

    for (int kk2 = 2; kk2 <= 128; kk2 <<= 1) {
        for (int jj = kk2 >> 1; jj > 0; jj >>= 1) {
            if (t < 128) {
                int ixj = t ^ jj;
                if (ixj > t) {
                    u64 a = sel[t], b = sel[ixj];
                    bool up = ((t & kk2) == 0);
                    if (up ? (a > b) : (a < b)) { sel[t] = b; sel[ixj] = a; }
                }
            }
            __syncthreads();
        }
    }

    // output buffer is float32 (indices exact below 2^24)
    if (t < TOPK) out[q * TOPK + t] = (float)(u32)(sel[t] & 0xFFFFFFFFu);
}

// =============================================================================
// launch — input mapping verified by round-7 diagnostics (dict order)
// =============================================================================
extern "C" void kernel_launch(void* const* d_in, const int* in_sizes, int n_in,
                              void* d_out, int out_size)
{
    const float* queries   = (const float*)d_in[0];
    const float* centroids = (const float*)d_in[1];
    const float* codebooks = (const float*)d_in[2];
    const int*   db_codes  = (const int*)d_in[3];
    const int*   db_list   = (const int*)d_in[4];
    int N = in_sizes[4];
    if (N <= 0 || N > MAXN) N = MAXN;
    float* out = (float*)d_out;

    cudaFuncSetAttribute(k_search, cudaFuncAttributeMaxDynamicSharedMemorySize,
                         DYN_SMEM);

    k_prep<<<256, 256>>>(centroids);
    k_hist<<<256, 256>>>(db_list, N);
    k_scan<<<1, 1024>>>();
    k_scatter<<<(N + 255) / 256, 256>>>(db_list, db_codes, N);
    k_search<<<QN, 256, DYN_SMEM>>>(queries, codebooks, out);
}

// round 15
// speedup vs baseline: 2.0052x; 1.0029x over previous
#include <cuda_runtime.h>
#include <stdint.h>

#define QN     256
#define DIM    128
#define NLIST  1024
#define MSUB   8
#define KCODE  256
#define DSUB   16
#define NPROBE 32
#define TOPK   100
#define MAXN   250000
#define CAP    12288
#define DYN_SMEM (CAP * 8)

typedef unsigned long long u64;
typedef unsigned int       u32;

// ---------------- device scratch (static: allocation-free) ------------------
__device__ float g_cnf[NLIST];          // centroid norms (XLA-reduce order)
__device__ float g_ct[DIM * NLIST];     // centroids transposed [d][l]
__device__ int   g_counts[NLIST];
__device__ int   g_starts[NLIST];
__device__ int   g_cursor[NLIST];
__device__ int   g_inv[MAXN];           // point id per inverted slot
__device__ int4  g_codes[2 * MAXN];     // codes gathered into inverted order

// monotonic float->uint transform (total order preserving)
__device__ __forceinline__ u32 f2s(float f) {
    u32 u = __float_as_uint(f);
    return u ^ ((u >> 31) ? 0xFFFFFFFFu : 0x80000000u);
}

// XLA-GPU style row-norm: lane sums 4 CONTIGUOUS rounded products
// sequentially, then shfl-down butterfly (16,8,4,2,1). Valid in lane 0.
__device__ __forceinline__ float warp_norm128(const float* __restrict__ row, int lane)
{
    float p0 = __fmul_rn(row[4 * lane + 0], row[4 * lane + 0]);
    float p1 = __fmul_rn(row[4 * lane + 1], row[4 * lane + 1]);
    float p2 = __fmul_rn(row[4 * lane + 2], row[4 * lane + 2]);
    float p3 = __fmul_rn(row[4 * lane + 3], row[4 * lane + 3]);
    float s  = __fadd_rn(__fadd_rn(__fadd_rn(p0, p1), p2), p3);
    #pragma unroll
    for (int off = 16; off > 0; off >>= 1)
        s = __fadd_rn(s, __shfl_down_sync(0xFFFFFFFFu, s, off));
    return s;
}

// ---------------- build: norms + transpose + zero counts ---------------------
__global__ void __launch_bounds__(256) k_prep(const float* __restrict__ centroids)
{
    int gw   = blockIdx.x * 8 + (threadIdx.x >> 5);
    int lane = threadIdx.x & 31;
    if (gw < NLIST) {
        float s = warp_norm128(centroids + (size_t)gw * DIM, lane);
        if (lane == 0) g_cnf[gw] = s;
    }
    int gtid = blockIdx.x * 256 + threadIdx.x;
    for (int i = gtid; i < DIM * NLIST; i += gridDim.x * 256) {
        int d = i >> 10, l = i & (NLIST - 1);
        g_ct[i] = __ldg(centroids + (size_t)l * DIM + d);
    }
    if (gtid < NLIST) g_counts[gtid] = 0;
}

__global__ void __launch_bounds__(256) k_hist(const int* __restrict__ db_list, int N)
{
    __shared__ int sh[NLIST];
    int t = threadIdx.x;
    for (int i = t; i < NLIST; i += 256) sh[i] = 0;
    __syncthreads();
    for (int n = blockIdx.x * 256 + t; n < N; n += gridDim.x * 256)
        atomicAdd(&sh[db_list[n] & (NLIST - 1)], 1);
    __syncthreads();
    for (int i = t; i < NLIST; i += 256)
        if (sh[i]) atomicAdd(&g_counts[i], sh[i]);
}

__global__ void __launch_bounds__(1024) k_scan()
{
    __shared__ int s[NLIST];
    int t = threadIdx.x;
    int c = g_counts[t];
    s[t] = c;
    __syncthreads();
    for (int off = 1; off < NLIST; off <<= 1) {
        int v = (t >= off) ? s[t - off] : 0;
        __syncthreads();
        s[t] += v;
        __syncthreads();
    }
    g_starts[t] = s[t] - c;
    g_cursor[t] = s[t] - c;
}

// 4 consecutive points per thread: int4 list load, 128B contiguous code read,
// 4 independent atomic chains in flight (MLP=4)
__global__ void __launch_bounds__(256) k_scatter(const int* __restrict__ db_list,
                                                 const int* __restrict__ db_codes,
                                                 int N)
{
    int base = (blockIdx.x * 256 + threadIdx.x) * 4;
    if (base >= N) return;
    if (base + 4 <= N) {
        int4 ls = __ldg((const int4*)(db_list + base));
        int l0 = ls.x & (NLIST - 1), l1 = ls.y & (NLIST - 1);
        int l2 = ls.z & (NLIST - 1), l3 = ls.w & (NLIST - 1);
        // 128 contiguous bytes of codes for the 4 points
        const int4* cp = (const int4*)(db_codes + (size_t)base * MSUB);
        int4 c0 = __ldg(cp),     c1 = __ldg(cp + 1);
        int4 c2 = __ldg(cp + 2), c3 = __ldg(cp + 3);
        int4 c4 = __ldg(cp + 4), c5 = __ldg(cp + 5);
        int4 c6 = __ldg(cp + 6), c7 = __ldg(cp + 7);
        int p0 = atomicAdd(&g_cursor[l0], 1);
        int p1 = atomicAdd(&g_cursor[l1], 1);
        int p2 = atomicAdd(&g_cursor[l2], 1);
        int p3 = atomicAdd(&g_cursor[l3], 1);
        g_inv[p0] = base;     g_codes[2 * p0] = c0; g_codes[2 * p0 + 1] = c1;
        g_inv[p1] = base + 1; g_codes[2 * p1] = c2; g_codes[2 * p1 + 1] = c3;
        g_inv[p2] = base + 2; g_codes[2 * p2] = c4; g_codes[2 * p2 + 1] = c5;
        g_inv[p3] = base + 3; g_codes[2 * p3] = c6; g_codes[2 * p3 + 1] = c7;
    } else {
        for (int n = base; n < N; ++n) {
            int l   = db_list[n] & (NLIST - 1);
            int pos = atomicAdd(&g_cursor[l], 1);
            const int4* cp = (const int4*)(db_codes + (size_t)n * MSUB);
            g_inv[pos] = n;
            g_codes[2 * pos]     = __ldg(cp);
            g_codes[2 * pos + 1] = __ldg(cp + 1);
        }
    }
}

// =============================================================================
// k_search: one CTA per query. Dynamic smem: CAP u64 candidate keys (96 KB).
//   phase 1: coarse dists, float4 reads of transposed centroids (4 lists/thread)
//   phase 2: ADC LUT (round-11 numerics)
//   phase 3: single walk of 32 inverted lists, coalesced g_codes reads
//   phase 4: exact radix select + compact + bitonic 128 -> top-100 (as float)
// =============================================================================
__global__ void __launch_bounds__(256) k_search(const float* __restrict__ queries,
                                                const float* __restrict__ codebooks,
                                                float* __restrict__ out)
{
    extern __shared__ u64 cand[];            // CAP keys

    __shared__ float lut[MSUB * KCODE];
    __shared__ float qsm[DIM];
    __shared__ u32   hist256[256];
    __shared__ u64   sel[128];
    __shared__ u64   wmin[8];
    __shared__ float s_qnf;
    __shared__ int   s_list[NPROBE], s_start[NPROBE], s_cn[NPROBE], s_pcum[NPROBE + 1];
    __shared__ int   s_cnt, s_k;
    __shared__ u32   s_pfx;

    int t = threadIdx.x;
    int q = blockIdx.x;

    if (t < DIM) qsm[t] = queries[q * DIM + t];
    __syncthreads();

    // ---------- phase 1: coarse distances, float4 coalesced reads ------------
    if (t < 32) {
        float s = warp_norm128(qsm, t);
        if (t == 0) s_qnf = s;
    }
    __syncthreads();
    float qnf = s_qnf;

    // thread t owns lists 4t .. 4t+3; one float4 load per dim
    float a0 = 0.f, a1 = 0.f, a2 = 0.f, a3 = 0.f;   // seq FMA, d ascending
    #pragma unroll 8
    for (int d = 0; d < DIM; ++d) {
        float qd = qsm[d];
        float4 c = __ldg((const float4*)(g_ct + d * NLIST) + t);
        a0 = __fmaf_rn(qd, c.x, a0);
        a1 = __fmaf_rn(qd, c.y, a1);
        a2 = __fmaf_rn(qd, c.z, a2);
        a3 = __fmaf_rn(qd, c.w, a3);
    }
    int l0 = 4 * t;
    float4 cn4 = __ldg((const float4*)(g_cnf) + t);
    u64 key[4];
    key[0] = (((u64)f2s(__fsub_rn(__fadd_rn(qnf, cn4.x), __fmul_rn(2.f, a0)))) << 32) | (u32)(l0);
    key[1] = (((u64)f2s(__fsub_rn(__fadd_rn(qnf, cn4.y), __fmul_rn(2.f, a1)))) << 32) | (u32)(l0 + 1);
    key[2] = (((u64)f2s(__fsub_rn(__fadd_rn(qnf, cn4.z), __fmul_rn(2.f, a2)))) << 32) | (u32)(l0 + 2);
    key[3] = (((u64)f2s(__fsub_rn(__fadd_rn(qnf, cn4.w), __fmul_rn(2.f, a3)))) << 32) | (u32)(l0 + 3);

    // exact top-32: 32 rounds of register argmin (keys unique)
    for (int r = 0; r < NPROBE; ++r) {
        u64 lm = key[0];
        #pragma unroll
        for (int s = 1; s < 4; ++s) if (key[s] < lm) lm = key[s];
        #pragma unroll
        for (int off = 16; off > 0; off >>= 1) {
            u64 o = __shfl_down_sync(0xFFFFFFFFu, lm, off);
            if (o < lm) lm = o;
        }
        if ((t & 31) == 0) wmin[t >> 5] = lm;
        __syncthreads();
        u64 g = wmin[0];
        #pragma unroll
        for (int w = 1; w < 8; ++w) if (wmin[w] < g) g = wmin[w];
        #pragma unroll
        for (int s = 0; s < 4; ++s)
            if (key[s] == g) key[s] = ~0ULL;
        if (t == 0) s_list[r] = (int)(g & (NLIST - 1));
        __syncthreads();                      // wmin reuse barrier
    }

    if (t < NPROBE) {
        int l = s_list[t];
        s_start[t] = g_starts[l];
        s_cn[t]    = g_counts[l];
    }
    __syncthreads();
    if (t == 0) {
        int acc = 0;
        for (int i = 0; i < NPROBE; ++i) { s_pcum[i] = acc; acc += s_cn[i]; }
        s_pcum[NPROBE] = acc;
    }

    // ---------- phase 2: ADC LUT (reference-order f32) -----------------------
    #pragma unroll
    for (int m = 0; m < MSUB; ++m) {
        const float* cb = codebooks + ((size_t)(m * KCODE + t)) * DSUB;
        const float* qm = qsm + m * DSUB;
        float cn = 0.f, qns = 0.f, dq = 0.f;
        #pragma unroll
        for (int d = 0; d < DSUB; ++d) {
            float c = __ldg(cb + d);
            cn  = __fadd_rn(cn,  __fmul_rn(c, c));
            qns = __fadd_rn(qns, __fmul_rn(qm[d], qm[d]));
            dq  = __fmaf_rn(qm[d], c, dq);
        }
        lut[m * KCODE + t] = __fsub_rn(__fadd_rn(qns, cn), __fmul_rn(2.f, dq));
    }
    __syncthreads();

    // ---------- phase 3: single walk, keys at deterministic slots ------------
    int total = s_pcum[NPROBE];
    int C = (total < CAP) ? total : CAP;
    #pragma unroll 1
    for (int i = 0; i < NPROBE; ++i) {
        int base = s_start[i], cnt = s_cn[i], slot0 = s_pcum[i];
        for (int j = t; j < cnt; j += 256) {
            int slot = slot0 + j;
            if (slot >= CAP) break;
            int4 c0 = g_codes[2 * (base + j)];       // coalesced
            int4 c1 = g_codes[2 * (base + j) + 1];
            float dsum = lut[c0.x & 255];            // sequential f32, m = 0..7
            dsum = __fadd_rn(dsum, lut[KCODE     + (c0.y & 255)]);
            dsum = __fadd_rn(dsum, lut[2 * KCODE + (c0.z & 255)]);
            dsum = __fadd_rn(dsum, lut[3 * KCODE + (c0.w & 255)]);
            dsum = __fadd_rn(dsum, lut[4 * KCODE + (c1.x & 255)]);
            dsum = __fadd_rn(dsum, lut[5 * KCODE + (c1.y & 255)]);
            dsum = __fadd_rn(dsum, lut[6 * KCODE + (c1.z & 255)]);
            dsum = __fadd_rn(dsum, lut[7 * KCODE + (c1.w & 255)]);
            cand[slot] = (((u64)f2s(dsum)) << 32) | (u32)g_inv[base + j];
        }
    }
    __syncthreads();

    int ksel = (C < TOPK) ? C : TOPK;
    if (C == 0) {
        if (t < TOPK) out[q * TOPK + t] = 0.f;   // unreachable for this data
        return;
    }

    // ---------- phase 4a: exact radix select of ksel-th smallest dist key ----
    if (t == 0) { s_pfx = 0u; s_k = ksel; }
    int iters = (C + 255) >> 8;
    for (int pass = 3; pass >= 0; --pass) {
        __syncthreads();
        u32 prefix = s_pfx;
        int kk     = s_k;
        int shift  = pass * 8;
        u32 pmask  = (pass == 3) ? 0u : (0xFFFFFFFFu << (shift + 8));
        hist256[t] = 0;
        __syncthreads();
        for (int it = 0; it < iters; ++it) {
            int j = (it << 8) + t;
            u32 b = 0xFFFFFFFFu;
            if (j < C) {
                u32 dk = (u32)(cand[j] >> 32);
                if ((dk & pmask) == prefix)
                    b = (dk >> shift) & 0xFF;
            }
            unsigned am = __activemask();
            u32 mm = __match_any_sync(am, b);
            if (b != 0xFFFFFFFFu) {
                int leader = __ffs(mm) - 1;
                if ((t & 31) == leader) atomicAdd(&hist256[b], (u32)__popc(mm));
            }
        }
        __syncthreads();
        for (int off = 1; off < 256; off <<= 1) {
            u32 v = (t >= off) ? hist256[t - off] : 0u;
            __syncthreads();
            hist256[t] += v;
            __syncthreads();
        }
        u32 cum  = hist256[t];
        u32 prev = (t == 0) ? 0u : hist256[t - 1];
        if ((int)cum >= kk && (int)prev < kk) {
            s_pfx = prefix | ((u32)t << shift);
            s_k   = kk - (int)prev;
        }
    }
    __syncthreads();
    u32 kth = s_pfx;

    // ---------- phase 4b: compact (<= kth), bitonic sort 128, emit -----------
    if (t == 0) s_cnt = 0;
    if (t < 128) sel[t] = ~0ULL;
    __syncthreads();
    for (int j = t; j < C; j += 256) {
        u64 k = cand[j];
        if ((u32)(k >> 32) <= kth) {
            int pos = atomicAdd(&s_cnt, 1);
            if (pos < 128) sel[pos] = k;
        }
    }
    __syncthreads();

    for (int kk2 = 2; kk2 <= 128; kk2 <<= 1) {
        for (int jj = kk2 >> 1; jj > 0; jj >>= 1) {
            if (t < 128) {
                int ixj = t ^ jj;
                if (ixj > t) {
                    u64 a = sel[t], b = sel[ixj];
                    bool up = ((t & kk2) == 0);
                    if (up ? (a > b) : (a < b)) { sel[t] = b; sel[ixj] = a; }
                }
            }
            __syncthreads();
        }
    }

    // output buffer is float32 (indices exact below 2^24)
    if (t < TOPK) out[q * TOPK + t] = (float)(u32)(sel[t] & 0xFFFFFFFFu);
}

// =============================================================================
// launch — input mapping verified by round-7 diagnostics (dict order)
// =============================================================================
extern "C" void kernel_launch(void* const* d_in, const int* in_sizes, int n_in,
                              void* d_out, int out_size)
{
    const float* queries   = (const float*)d_in[0];
    const float* centroids = (const float*)d_in[1];
    const float* codebooks = (const float*)d_in[2];
    const int*   db_codes  = (const int*)d_in[3];
    const int*   db_list   = (const int*)d_in[4];
    int N = in_sizes[4];
    if (N <= 0 || N > MAXN) N = MAXN;
    float* out = (float*)d_out;

    cudaFuncSetAttribute(k_search, cudaFuncAttributeMaxDynamicSharedMemorySize,
                         DYN_SMEM);

    k_prep<<<256, 256>>>(centroids);
    k_hist<<<256, 256>>>(db_list, N);
    k_scan<<<1, 1024>>>();
    k_scatter<<<(N + 1023) / 1024, 256>>>(db_list, db_codes, N);
    k_search<<<QN, 256, DYN_SMEM>>>(queries, codebooks, out);
}